// round 2
// baseline (speedup 1.0000x reference)
#include <cuda_runtime.h>
#include <cuda_bf16.h>
#include <cstdint>

#define BB   16
#define LL   128
#define EE   256
#define HH   256
#define H4   1024
#define RRr  128
#define BIOd 64
#define NTAG 3
#define RREL 25
#define ML   (BB*LL)   // 2048

typedef unsigned long long u64;

// ---------- packed fp32x2 helpers ----------
__device__ __forceinline__ u64 pk2(float lo, float hi) {
    u64 r; asm("mov.b64 %0,{%1,%2};" : "=l"(r) : "f"(lo), "f"(hi)); return r;
}
__device__ __forceinline__ void upk2(u64 v, float &lo, float &hi) {
    asm("mov.b64 {%0,%1},%2;" : "=f"(lo), "=f"(hi) : "l"(v));
}
__device__ __forceinline__ void fma2(u64 &acc, u64 a, u64 b) {
    asm("fma.rn.f32x2 %0,%1,%2,%0;" : "+l"(acc) : "l"(a), "l"(b));
}

// ---------- device scratch (no allocations allowed) ----------
__device__ float g_emb[ML * EE];
__device__ float g_xg0[ML * H4];
__device__ float g_xg1[ML * H4];
__device__ float g_h0[ML * HH];
__device__ float g_h1[ML * HH];
__device__ float g_oc[ML * (HH + BIOd)];
__device__ float g_emi[ML * NTAG];
__device__ float g_u[ML * RRr];
__device__ float g_v[ML * RRr];
__device__ float g_a[ML * RRr];
__device__ float g_c[ML * RRr];
__device__ float g_crf[BB];
__device__ float g_msum[BB];
__device__ float g_selpart[1024];

// ---------- 1) embedding gather ----------
__global__ void k_embed(const int *__restrict__ tokens, const float *__restrict__ wemb) {
    int m = blockIdx.x, t = threadIdx.x;               // 2048 x 64
    size_t tok = (size_t)tokens[m];
    ((float4 *)(g_emb + (size_t)m * EE))[t] = ((const float4 *)(wemb + tok * EE))[t];
}

// ---------- 2) C[M,N] = A[M,K] @ W[N,K]^T (+bias)(+relu), 64x64 tile ----------
template <bool RELU, bool HASB>
__global__ __launch_bounds__(256) void k_gemm(
    const float *__restrict__ A, int lda,
    const float *__restrict__ W, int ldw,
    const float *__restrict__ bias,
    float *__restrict__ C, int ldc, int K)
{
    __shared__ __align__(16) float As[16][68];
    __shared__ __align__(16) float Ws[16][68];
    const int tid = threadIdx.x;
    const int m0 = blockIdx.y * 64, n0 = blockIdx.x * 64;
    const int tx = tid & 15, ty = tid >> 4;
    const int r = tid >> 2, cq = (tid & 3) * 4;
    u64 acc[4][2] = {};
    for (int kt = 0; kt < K; kt += 16) {
        float4 av = *(const float4 *)&A[(size_t)(m0 + r) * lda + kt + cq];
        float4 wv = *(const float4 *)&W[(size_t)(n0 + r) * ldw + kt + cq];
        As[cq + 0][r] = av.x; As[cq + 1][r] = av.y; As[cq + 2][r] = av.z; As[cq + 3][r] = av.w;
        Ws[cq + 0][r] = wv.x; Ws[cq + 1][r] = wv.y; Ws[cq + 2][r] = wv.z; Ws[cq + 3][r] = wv.w;
        __syncthreads();
#pragma unroll
        for (int k = 0; k < 16; k++) {
            float4 a4 = *(const float4 *)&As[k][ty * 4];
            ulonglong2 w2 = *(const ulonglong2 *)&Ws[k][tx * 4];
            u64 a0 = pk2(a4.x, a4.x), a1 = pk2(a4.y, a4.y);
            u64 a2 = pk2(a4.z, a4.z), a3 = pk2(a4.w, a4.w);
            fma2(acc[0][0], a0, w2.x); fma2(acc[0][1], a0, w2.y);
            fma2(acc[1][0], a1, w2.x); fma2(acc[1][1], a1, w2.y);
            fma2(acc[2][0], a2, w2.x); fma2(acc[2][1], a2, w2.y);
            fma2(acc[3][0], a3, w2.x); fma2(acc[3][1], a3, w2.y);
        }
        __syncthreads();
    }
#pragma unroll
    for (int i = 0; i < 4; i++) {
        int m = m0 + ty * 4 + i;
#pragma unroll
        for (int j = 0; j < 2; j++) {
            float lo, hi; upk2(acc[i][j], lo, hi);
            int n = n0 + tx * 4 + j * 2;
            if (HASB) { lo += bias[n]; hi += bias[n + 1]; }
            if (RELU) { lo = fmaxf(lo, 0.f); hi = fmaxf(hi, 0.f); }
            C[(size_t)m * ldc + n]     = lo;
            C[(size_t)m * ldc + n + 1] = hi;
        }
    }
}

// ---------- 3) LSTM scan: one CTA per (direction, batch) ----------
__global__ __launch_bounds__(1024, 1) void k_lstm(
    const float *__restrict__ Wf, const float *__restrict__ Wb)
{
    const int d = blockIdx.x >> 4, b = blockIdx.x & 15;
    const float *W  = d ? Wb : Wf;
    const float *xg = d ? g_xg1 : g_xg0;
    float *hout     = d ? g_h1 : g_h0;
    __shared__ __align__(16) float h_sh[HH];
    __shared__ float gsh[H4];
    const int r = threadIdx.x;
    float c_reg = 0.f;
    if (r < HH) h_sh[r] = 0.f;
    __syncthreads();
    const ulonglong2 *Wr = (const ulonglong2 *)(W + (size_t)r * HH);
    for (int step = 0; step < LL; step++) {
        int l = d ? (LL - 1 - step) : step;
        u64 acc = 0ull, acc2 = 0ull;
        const ulonglong2 *H2 = (const ulonglong2 *)h_sh;
#pragma unroll 4
        for (int k = 0; k < HH / 4; k++) {
            ulonglong2 w = Wr[k], h = H2[k];
            fma2(acc, w.x, h.x); fma2(acc2, w.y, h.y);
        }
        float lo, hi, lo2, hi2; upk2(acc, lo, hi); upk2(acc2, lo2, hi2);
        gsh[r] = xg[(size_t)(b * LL + l) * H4 + r] + lo + hi + lo2 + hi2;
        __syncthreads();
        if (r < HH) {
            float gi = gsh[r], gf = gsh[HH + r], gg = gsh[2 * HH + r], go = gsh[3 * HH + r];
            float si = 1.f / (1.f + __expf(-gi));
            float sf = 1.f / (1.f + __expf(-gf));
            float so = 1.f / (1.f + __expf(-go));
            c_reg = sf * c_reg + si * tanhf(gg);
            float hn = so * tanhf(c_reg);
            h_sh[r] = hn;
            hout[(size_t)(b * LL + l) * HH + r] = hn;
        }
        __syncthreads();
    }
}

// ---------- 4) o = 0.5*(hf+hb); oc = [o, bio_emb[bio]]; emi = o @ emi_W.T + b ----------
__global__ __launch_bounds__(256) void k_combine(
    const int *__restrict__ bio, const float *__restrict__ bio_emb,
    const float *__restrict__ emiW, const float *__restrict__ emib)
{
    int m = blockIdx.x, t = threadIdx.x;
    __shared__ float osh[HH];
    float o = 0.5f * (g_h0[(size_t)m * HH + t] + g_h1[(size_t)m * HH + t]);
    g_oc[(size_t)m * (HH + BIOd) + t] = o;
    osh[t] = o;
    if (t < BIOd) g_oc[(size_t)m * (HH + BIOd) + HH + t] = bio_emb[bio[m] * BIOd + t];
    __syncthreads();
    int w = t >> 5, lane = t & 31;
    if (w < NTAG) {
        float s = 0.f;
        for (int k = lane; k < HH; k += 32) s += osh[k] * emiW[w * HH + k];
#pragma unroll
        for (int off = 16; off; off >>= 1) s += __shfl_down_sync(0xffffffffu, s, off);
        if (lane == 0) g_emi[m * NTAG + w] = s + emib[w];
    }
}

// ---------- 5) CRF loss: one warp per batch ----------
__global__ __launch_bounds__(512) void k_crf(
    const int *__restrict__ tokens, const int *__restrict__ bio,
    const float *__restrict__ cs, const float *__restrict__ ce, const float *__restrict__ ct)
{
    int b = threadIdx.x >> 5, lane = threadIdx.x & 31;
    if (b >= BB) return;
    const float *emi = g_emi + b * LL * NTAG;
    const int *tok = tokens + b * LL;
    const int *bg  = bio + b * LL;
    // numerator partials over l, lanes in parallel
    float np = 0.f; int mcount = 0;
    for (int l = lane; l < LL; l += 32) {
        int m = (tok[l] != 0);
        mcount += m;
        if (l >= 1 && m) {
            int yp = bg[l - 1], y = bg[l];
            np += ct[yp * NTAG + y] + emi[l * NTAG + y];
        }
    }
#pragma unroll
    for (int o = 16; o; o >>= 1) {
        np += __shfl_down_sync(0xffffffffu, np, o);
        mcount += __shfl_down_sync(0xffffffffu, mcount, o);
    }
    np = __shfl_sync(0xffffffffu, np, 0);
    mcount = __shfl_sync(0xffffffffu, mcount, 0);
    // denominator forward scan, lanes 0..2 hold score[j]
    int j = lane < 3 ? lane : 2;
    float c0 = ct[0 * NTAG + j], c1 = ct[1 * NTAG + j], c2 = ct[2 * NTAG + j];
    float s = cs[j] + emi[0 * NTAG + j];
    for (int l = 1; l < LL; l++) {
        float s0 = __shfl_sync(0xffffffffu, s, 0);
        float s1 = __shfl_sync(0xffffffffu, s, 1);
        float s2 = __shfl_sync(0xffffffffu, s, 2);
        float v0 = s0 + c0, v1 = s1 + c1, v2 = s2 + c2;
        float mx = fmaxf(v0, fmaxf(v1, v2));
        float lse = mx + __logf(__expf(v0 - mx) + __expf(v1 - mx) + __expf(v2 - mx));
        float nxt = lse + emi[l * NTAG + j];
        s = (tok[l] != 0) ? nxt : s;
    }
    float f = s + ce[j];
    float f0 = __shfl_sync(0xffffffffu, f, 0);
    float f1 = __shfl_sync(0xffffffffu, f, 1);
    float f2 = __shfl_sync(0xffffffffu, f, 2);
    if (lane == 0) {
        float mx = fmaxf(f0, fmaxf(f1, f2));
        float den = mx + __logf(__expf(f0 - mx) + __expf(f1 - mx) + __expf(f2 - mx));
        int y0 = bg[0];
        float num = cs[y0] + emi[0 * NTAG + y0] + np;
        int se = mcount > 0 ? mcount - 1 : 0;
        num += ce[bg[se]];
        g_crf[b]  = num - den;
        g_msum[b] = (float)mcount;
    }
}

// ---------- 6) selection: fused uv-relu + 25-way dot + BCE ----------
__global__ __launch_bounds__(256) void k_sel(
    const float *__restrict__ gold, const int *__restrict__ tokens,
    const float *__restrict__ bias, const float *__restrict__ rel)
{
    const int b = blockIdx.z, i0 = blockIdx.y * 16, j0 = blockIdx.x * 16;
    __shared__ float Ash[16][130];
    __shared__ float Csh[16][130];
    __shared__ __align__(8) float Rsh[RREL * 128];
    __shared__ float mA[16], mC[16];
    __shared__ float red[8];
    const int tid = threadIdx.x;
    for (int v = tid; v < 16 * 128; v += 256) {
        int row = v >> 7, col = v & 127;
        Ash[row][col] = g_a[(size_t)(b * LL + j0 + row) * RRr + col] + bias[col];
        Csh[row][col] = g_c[(size_t)(b * LL + i0 + row) * RRr + col];
    }
    for (int v = tid; v < RREL * 128; v += 256) Rsh[v] = rel[v];
    if (tid < 16)      mA[tid]      = (tokens[b * LL + j0 + tid] != 0) ? 1.f : 0.f;
    else if (tid < 32) mC[tid - 16] = (tokens[b * LL + i0 + tid - 16] != 0) ? 1.f : 0.f;
    __syncthreads();

    const int il = tid >> 4, jl = tid & 15;
    u64 acc[RREL];
#pragma unroll
    for (int q = 0; q < RREL; q++) acc[q] = 0ull;
#pragma unroll 2
    for (int h = 0; h < 128; h += 2) {
        float u0 = fmaxf(Ash[jl][h]     + Csh[il][h],     0.f);
        float u1 = fmaxf(Ash[jl][h + 1] + Csh[il][h + 1], 0.f);
        u64 up = pk2(u0, u1);
#pragma unroll
        for (int q = 0; q < RREL; q++)
            fma2(acc[q], up, *(const u64 *)(Rsh + q * 128 + h));
    }
    float msk = mA[jl] * mC[il];
    float s = 0.f;
    size_t base = (size_t)(b * LL + i0 + il) * RREL * LL + j0 + jl;
#pragma unroll
    for (int q = 0; q < RREL; q++) {
        float lo, hi; upk2(acc[q], lo, hi);
        float lg = lo + hi;
        float y = gold[base + (size_t)q * LL];
        s += fmaxf(lg, 0.f) - lg * y + __logf(1.f + __expf(-fabsf(lg)));
    }
    s *= msk;
#pragma unroll
    for (int o = 16; o; o >>= 1) s += __shfl_down_sync(0xffffffffu, s, o);
    if ((tid & 31) == 0) red[tid >> 5] = s;
    __syncthreads();
    if (tid == 0) {
        float t = 0.f;
#pragma unroll
        for (int w = 0; w < 8; w++) t += red[w];
        g_selpart[(blockIdx.z * 8 + blockIdx.y) * 8 + blockIdx.x] = t;
    }
}

// ---------- 7) deterministic final reduction ----------
__global__ __launch_bounds__(256) void k_final(float *out) {
    __shared__ float sh[256];
    int tid = threadIdx.x;
    float s = 0.f;
    for (int v = tid; v < 1024; v += 256) s += g_selpart[v];
    sh[tid] = s; __syncthreads();
    for (int o = 128; o; o >>= 1) { if (tid < o) sh[tid] += sh[tid + o]; __syncthreads(); }
    if (tid == 0) {
        float crf = 0.f, ms = 0.f;
        for (int b2 = 0; b2 < BB; b2++) { crf += g_crf[b2]; ms += g_msum[b2]; }
        out[0] = -(crf / (float)BB) + sh[0] / ms;
    }
}

extern "C" void kernel_launch(void* const* d_in, const int* in_sizes, int n_in,
                              void* d_out, int out_size) {
    const int   *tokens = (const int  *)d_in[0];
    const int   *bio    = (const int  *)d_in[1];
    const float *gold   = (const float*)d_in[2];
    const float *wemb   = (const float*)d_in[3];
    const float *Wihf   = (const float*)d_in[4];
    const float *Whhf   = (const float*)d_in[5];
    const float *bf     = (const float*)d_in[6];
    const float *Wihb   = (const float*)d_in[7];
    const float *Whhb   = (const float*)d_in[8];
    const float *bbv    = (const float*)d_in[9];
    const float *emiW   = (const float*)d_in[10];
    const float *emib   = (const float*)d_in[11];
    const float *bioemb = (const float*)d_in[12];
    const float *suW    = (const float*)d_in[13];
    const float *sub    = (const float*)d_in[14];
    const float *svW    = (const float*)d_in[15];
    const float *svb    = (const float*)d_in[16];
    const float *suvW   = (const float*)d_in[17];
    const float *suvb   = (const float*)d_in[18];
    const float *rel    = (const float*)d_in[19];
    const float *cs     = (const float*)d_in[20];
    const float *ce     = (const float*)d_in[21];
    const float *ct     = (const float*)d_in[22];
    float *out = (float *)d_out;

    float *p_emb, *p_xg0, *p_xg1, *p_oc, *p_u, *p_v, *p_a, *p_c;
    cudaGetSymbolAddress((void**)&p_emb, g_emb);
    cudaGetSymbolAddress((void**)&p_xg0, g_xg0);
    cudaGetSymbolAddress((void**)&p_xg1, g_xg1);
    cudaGetSymbolAddress((void**)&p_oc,  g_oc);
    cudaGetSymbolAddress((void**)&p_u,   g_u);
    cudaGetSymbolAddress((void**)&p_v,   g_v);
    cudaGetSymbolAddress((void**)&p_a,   g_a);
    cudaGetSymbolAddress((void**)&p_c,   g_c);

    k_embed<<<ML, 64>>>(tokens, wemb);
    k_gemm<false, true><<<dim3(H4/64, ML/64), 256>>>(p_emb, EE, Wihf, EE, bf,  p_xg0, H4, EE);
    k_gemm<false, true><<<dim3(H4/64, ML/64), 256>>>(p_emb, EE, Wihb, EE, bbv, p_xg1, H4, EE);
    k_lstm<<<32, 1024>>>(Whhf, Whhb);
    k_combine<<<ML, 256>>>(bio, bioemb, emiW, emib);
    k_gemm<true,  true><<<dim3(RRr/64, ML/64), 256>>>(p_oc, HH+BIOd, suW, HH+BIOd, sub, p_u, RRr, HH+BIOd);
    k_gemm<true,  true><<<dim3(RRr/64, ML/64), 256>>>(p_oc, HH+BIOd, svW, HH+BIOd, svb, p_v, RRr, HH+BIOd);
    k_gemm<false, false><<<dim3(RRr/64, ML/64), 256>>>(p_u, RRr, suvW,        2*RRr, nullptr, p_a, RRr, RRr);
    k_gemm<false, false><<<dim3(RRr/64, ML/64), 256>>>(p_v, RRr, suvW + RRr,  2*RRr, nullptr, p_c, RRr, RRr);
    k_crf<<<1, 512>>>(tokens, bio, cs, ce, ct);
    k_sel<<<dim3(8, 8, BB), 256>>>(gold, tokens, suvb, rel);
    k_final<<<1, 256>>>(out);
}

// round 10
// speedup vs baseline: 6.4929x; 6.4929x over previous
#include <cuda_runtime.h>
#include <cuda_bf16.h>
#include <cstdint>

#define BB   16
#define LL   128
#define EE   256
#define HH   256
#define H4   1024
#define RRr  128
#define BIOd 64
#define NTAG 3
#define RREL 25
#define ML   (BB*LL)   // 2048

typedef unsigned long long u64;

// ---------- packed fp32x2 helpers ----------
__device__ __forceinline__ u64 pk2(float lo, float hi) {
    u64 r; asm("mov.b64 %0,{%1,%2};" : "=l"(r) : "f"(lo), "f"(hi)); return r;
}
__device__ __forceinline__ void upk2(u64 v, float &lo, float &hi) {
    asm("mov.b64 {%0,%1},%2;" : "=f"(lo), "=f"(hi) : "l"(v));
}
__device__ __forceinline__ void fma2(u64 &acc, u64 a, u64 b) {
    asm("fma.rn.f32x2 %0,%1,%2,%0;" : "+l"(acc) : "l"(a), "l"(b));
}
__device__ __forceinline__ float tanh_fast(float x) {
    float r; asm("tanh.approx.f32 %0, %1;" : "=f"(r) : "f"(x)); return r;
}
__device__ __forceinline__ uint32_t smem_u32(const void *p) {
    uint32_t a;
    asm("{ .reg .u64 t; cvta.to.shared.u64 t, %1; cvt.u32.u64 %0, t; }" : "=r"(a) : "l"(p));
    return a;
}

// ---------- device scratch ----------
__device__ float g_emb[ML * EE];
__device__ float g_xg0[ML * H4];
__device__ float g_xg1[ML * H4];
__device__ float g_h0[ML * HH];
__device__ float g_h1[ML * HH];
__device__ float g_oc[ML * (HH + BIOd)];
__device__ float g_emi[ML * NTAG];
__device__ float g_u[ML * RRr];
__device__ float g_v[ML * RRr];
__device__ float g_a[ML * RRr];
__device__ float g_c[ML * RRr];
__device__ float g_crf[BB];
__device__ float g_msum[BB];
__device__ float g_selpart[1024];

// ---------- 1) embedding gather ----------
__global__ void k_embed(const int *__restrict__ tokens, const float *__restrict__ wemb) {
    int m = blockIdx.x, t = threadIdx.x;
    size_t tok = (size_t)tokens[m];
    ((float4 *)(g_emb + (size_t)m * EE))[t] = ((const float4 *)(wemb + tok * EE))[t];
}

// ---------- 2) C[M,N] = A[M,K] @ W[N,K]^T (+bias)(+relu), 64x64 tile ----------
template <bool RELU, bool HASB>
__global__ __launch_bounds__(256) void k_gemm(
    const float *__restrict__ A, int lda,
    const float *__restrict__ W, int ldw,
    const float *__restrict__ bias,
    float *__restrict__ C, int ldc, int K)
{
    __shared__ __align__(16) float As[16][68];
    __shared__ __align__(16) float Ws[16][68];
    const int tid = threadIdx.x;
    const int m0 = blockIdx.y * 64, n0 = blockIdx.x * 64;
    const int tx = tid & 15, ty = tid >> 4;
    const int r = tid >> 2, cq = (tid & 3) * 4;
    u64 acc[4][2] = {};
    for (int kt = 0; kt < K; kt += 16) {
        float4 av = *(const float4 *)&A[(size_t)(m0 + r) * lda + kt + cq];
        float4 wv = *(const float4 *)&W[(size_t)(n0 + r) * ldw + kt + cq];
        As[cq + 0][r] = av.x; As[cq + 1][r] = av.y; As[cq + 2][r] = av.z; As[cq + 3][r] = av.w;
        Ws[cq + 0][r] = wv.x; Ws[cq + 1][r] = wv.y; Ws[cq + 2][r] = wv.z; Ws[cq + 3][r] = wv.w;
        __syncthreads();
#pragma unroll
        for (int k = 0; k < 16; k++) {
            float4 a4 = *(const float4 *)&As[k][ty * 4];
            ulonglong2 w2 = *(const ulonglong2 *)&Ws[k][tx * 4];
            u64 a0 = pk2(a4.x, a4.x), a1 = pk2(a4.y, a4.y);
            u64 a2 = pk2(a4.z, a4.z), a3 = pk2(a4.w, a4.w);
            fma2(acc[0][0], a0, w2.x); fma2(acc[0][1], a0, w2.y);
            fma2(acc[1][0], a1, w2.x); fma2(acc[1][1], a1, w2.y);
            fma2(acc[2][0], a2, w2.x); fma2(acc[2][1], a2, w2.y);
            fma2(acc[3][0], a3, w2.x); fma2(acc[3][1], a3, w2.y);
        }
        __syncthreads();
    }
#pragma unroll
    for (int i = 0; i < 4; i++) {
        int m = m0 + ty * 4 + i;
#pragma unroll
        for (int j = 0; j < 2; j++) {
            float lo, hi; upk2(acc[i][j], lo, hi);
            int n = n0 + tx * 4 + j * 2;
            if (HASB) { lo += bias[n]; hi += bias[n + 1]; }
            if (RELU) { lo = fmaxf(lo, 0.f); hi = fmaxf(hi, 0.f); }
            C[(size_t)m * ldc + n]     = lo;
            C[(size_t)m * ldc + n + 1] = hi;
        }
    }
}

// ---------- 3) LSTM: cluster-of-8, W_hh slice resident in SMEM ----------
#define PADW 268
#define OFF_W  0
#define OFF_H  (128*PADW)            // two buffers of 4*PADW
#define OFF_G  (OFF_H + 2*4*PADW)    // 4*132
#define OFF_HS (OFF_G + 4*132)       // 128 floats
#define LSTM_SMEM ((OFF_HS + 128) * 4)

__global__ void __cluster_dims__(8, 1, 1) __launch_bounds__(512, 1)
k_lstm2(const float *__restrict__ Wf, const float *__restrict__ Wb)
{
    extern __shared__ float smem[];
    float *sW  = smem + OFF_W;
    float *sG  = smem + OFF_G;
    float *sHS = smem + OFF_HS;

    const int tid = threadIdx.x;
    const int cid = blockIdx.x >> 3;
    const int dir = cid >> 2, grp = cid & 3;
    const int q   = blockIdx.x & 7;
    const float *W  = dir ? Wb : Wf;
    const float *xg = dir ? g_xg1 : g_xg0;
    float *hout     = dir ? g_h1 : g_h0;

    // load W slice: local row lr = gate*32+uu -> global row gate*256 + q*32 + uu
    {
        const float4 *Wg = (const float4 *)W;
        float4 *Ws4 = (float4 *)sW;
        for (int i = tid; i < 128 * 64; i += 512) {
            int lr = i >> 6, c4 = i & 63;
            int grow = (lr >> 5) * 256 + q * 32 + (lr & 31);
            Ws4[lr * (PADW / 4) + c4] = Wg[grow * 64 + c4];
        }
    }
    for (int i = tid; i < 4 * PADW; i += 512) smem[OFF_H + i] = 0.f;
    __syncthreads();
    asm volatile("barrier.cluster.arrive.aligned;" ::: "memory");
    asm volatile("barrier.cluster.wait.aligned;" ::: "memory");

    const int r = tid >> 2;        // local W row 0..127 (gate*32+unit)
    const int b = tid & 3;         // local batch 0..3
    const int grow = (r >> 5) * 256 + q * 32 + (r & 31);
    const int b_glob = grp * 4 + b;

    const int uu2 = tid >> 2;      // gate-combine mapping (tid<128): unit 0..31
    const int b2  = tid & 3;
    const int b_glob2 = grp * 4 + b2;

    float c_reg = 0.f;
    int par = 0;

    const ulonglong2 *Wr = (const ulonglong2 *)(sW + r * PADW);

    for (int step = 0; step < LL; step++) {
        int l = dir ? (LL - 1 - step) : step;
        float xv = __ldg(&xg[(size_t)(b_glob * LL + l) * H4 + grow]);

        const ulonglong2 *Hr = (const ulonglong2 *)(smem + OFF_H + par * 4 * PADW + b * PADW);
        u64 acc = 0ull, acc2 = 0ull;
#pragma unroll 8
        for (int k = 0; k < 64; k++) {
            ulonglong2 w = Wr[k], h = Hr[k];
            fma2(acc, w.x, h.x); fma2(acc2, w.y, h.y);
        }
        float lo, hi, lo2, hi2; upk2(acc, lo, hi); upk2(acc2, lo2, hi2);
        sG[b * 132 + r] = xv + lo + hi + lo2 + hi2;
        __syncthreads();

        if (tid < 128) {
            float gi = sG[b2 * 132 + uu2];
            float gf = sG[b2 * 132 + 32 + uu2];
            float gg = sG[b2 * 132 + 64 + uu2];
            float go = sG[b2 * 132 + 96 + uu2];
            float si = 1.f / (1.f + __expf(-gi));
            float sf = 1.f / (1.f + __expf(-gf));
            float so = 1.f / (1.f + __expf(-go));
            c_reg = sf * c_reg + si * tanh_fast(gg);
            float hn = so * tanh_fast(c_reg);
            sHS[b2 * 32 + uu2] = hn;
            hout[(size_t)(b_glob2 * LL + l) * HH + q * 32 + uu2] = hn;
        }
        __syncthreads();

        // broadcast own 32 units (4 batches) to all 8 CTAs' next h buffer
        if (tid < 32) {
            int b3 = tid >> 3, f4 = tid & 7;
            float4 v = *(const float4 *)&sHS[b3 * 32 + f4 * 4];
            uint32_t loc = smem_u32(smem + OFF_H + (par ^ 1) * 4 * PADW + b3 * PADW + q * 32 + f4 * 4);
#pragma unroll
            for (int rk = 0; rk < 8; rk++) {
                uint32_t rmt;
                asm("mapa.shared::cluster.u32 %0, %1, %2;" : "=r"(rmt) : "r"(loc), "r"(rk));
                asm volatile("st.shared::cluster.v4.f32 [%0], {%1,%2,%3,%4};"
                             :: "r"(rmt), "f"(v.x), "f"(v.y), "f"(v.z), "f"(v.w) : "memory");
            }
        }
        asm volatile("barrier.cluster.arrive.aligned;" ::: "memory");
        asm volatile("barrier.cluster.wait.aligned;" ::: "memory");
        par ^= 1;
    }
}

// ---------- 4) combine + emission ----------
__global__ __launch_bounds__(256) void k_combine(
    const int *__restrict__ bio, const float *__restrict__ bio_emb,
    const float *__restrict__ emiW, const float *__restrict__ emib)
{
    int m = blockIdx.x, t = threadIdx.x;
    __shared__ float osh[HH];
    float o = 0.5f * (g_h0[(size_t)m * HH + t] + g_h1[(size_t)m * HH + t]);
    g_oc[(size_t)m * (HH + BIOd) + t] = o;
    osh[t] = o;
    if (t < BIOd) g_oc[(size_t)m * (HH + BIOd) + HH + t] = bio_emb[bio[m] * BIOd + t];
    __syncthreads();
    int w = t >> 5, lane = t & 31;
    if (w < NTAG) {
        float s = 0.f;
        for (int k = lane; k < HH; k += 32) s += osh[k] * emiW[w * HH + k];
#pragma unroll
        for (int off = 16; off; off >>= 1) s += __shfl_down_sync(0xffffffffu, s, off);
        if (lane == 0) g_emi[m * NTAG + w] = s + emib[w];
    }
}

// ---------- 5) CRF loss ----------
__global__ __launch_bounds__(512) void k_crf(
    const int *__restrict__ tokens, const int *__restrict__ bio,
    const float *__restrict__ cs, const float *__restrict__ ce, const float *__restrict__ ct)
{
    int b = threadIdx.x >> 5, lane = threadIdx.x & 31;
    if (b >= BB) return;
    const float *emi = g_emi + b * LL * NTAG;
    const int *tok = tokens + b * LL;
    const int *bg  = bio + b * LL;
    float np = 0.f; int mcount = 0;
    for (int l = lane; l < LL; l += 32) {
        int m = (tok[l] != 0);
        mcount += m;
        if (l >= 1 && m) {
            int yp = bg[l - 1], y = bg[l];
            np += ct[yp * NTAG + y] + emi[l * NTAG + y];
        }
    }
#pragma unroll
    for (int o = 16; o; o >>= 1) {
        np += __shfl_down_sync(0xffffffffu, np, o);
        mcount += __shfl_down_sync(0xffffffffu, mcount, o);
    }
    np = __shfl_sync(0xffffffffu, np, 0);
    mcount = __shfl_sync(0xffffffffu, mcount, 0);
    int j = lane < 3 ? lane : 2;
    float c0 = ct[0 * NTAG + j], c1 = ct[1 * NTAG + j], c2 = ct[2 * NTAG + j];
    float s = cs[j] + emi[0 * NTAG + j];
    for (int l = 1; l < LL; l++) {
        float s0 = __shfl_sync(0xffffffffu, s, 0);
        float s1 = __shfl_sync(0xffffffffu, s, 1);
        float s2 = __shfl_sync(0xffffffffu, s, 2);
        float v0 = s0 + c0, v1 = s1 + c1, v2 = s2 + c2;
        float mx = fmaxf(v0, fmaxf(v1, v2));
        float lse = mx + __logf(__expf(v0 - mx) + __expf(v1 - mx) + __expf(v2 - mx));
        float nxt = lse + emi[l * NTAG + j];
        s = (tok[l] != 0) ? nxt : s;
    }
    float f = s + ce[j];
    float f0 = __shfl_sync(0xffffffffu, f, 0);
    float f1 = __shfl_sync(0xffffffffu, f, 1);
    float f2 = __shfl_sync(0xffffffffu, f, 2);
    if (lane == 0) {
        float mx = fmaxf(f0, fmaxf(f1, f2));
        float den = mx + __logf(__expf(f0 - mx) + __expf(f1 - mx) + __expf(f2 - mx));
        int y0 = bg[0];
        float num = cs[y0] + emi[0 * NTAG + y0] + np;
        int se = mcount > 0 ? mcount - 1 : 0;
        num += ce[bg[se]];
        g_crf[b]  = num - den;
        g_msum[b] = (float)mcount;
    }
}

// ---------- 6) selection ----------
__global__ __launch_bounds__(256) void k_sel(
    const float *__restrict__ gold, const int *__restrict__ tokens,
    const float *__restrict__ bias, const float *__restrict__ rel)
{
    const int b = blockIdx.z, i0 = blockIdx.y * 16, j0 = blockIdx.x * 16;
    __shared__ float Ash[16][130];
    __shared__ float Csh[16][130];
    __shared__ __align__(8) float Rsh[RREL * 128];
    __shared__ float mA[16], mC[16];
    __shared__ float red[8];
    const int tid = threadIdx.x;
    for (int v = tid; v < 16 * 128; v += 256) {
        int row = v >> 7, col = v & 127;
        Ash[row][col] = g_a[(size_t)(b * LL + j0 + row) * RRr + col] + bias[col];
        Csh[row][col] = g_c[(size_t)(b * LL + i0 + row) * RRr + col];
    }
    for (int v = tid; v < RREL * 128; v += 256) Rsh[v] = rel[v];
    if (tid < 16)      mA[tid]      = (tokens[b * LL + j0 + tid] != 0) ? 1.f : 0.f;
    else if (tid < 32) mC[tid - 16] = (tokens[b * LL + i0 + tid - 16] != 0) ? 1.f : 0.f;
    __syncthreads();

    const int il = tid >> 4, jl = tid & 15;
    u64 acc[RREL];
#pragma unroll
    for (int q = 0; q < RREL; q++) acc[q] = 0ull;
#pragma unroll 2
    for (int h = 0; h < 128; h += 2) {
        float u0 = fmaxf(Ash[jl][h]     + Csh[il][h],     0.f);
        float u1 = fmaxf(Ash[jl][h + 1] + Csh[il][h + 1], 0.f);
        u64 up = pk2(u0, u1);
#pragma unroll
        for (int q = 0; q < RREL; q++)
            fma2(acc[q], up, *(const u64 *)(Rsh + q * 128 + h));
    }
    float msk = mA[jl] * mC[il];
    float s = 0.f;
    size_t base = (size_t)(b * LL + i0 + il) * RREL * LL + j0 + jl;
#pragma unroll
    for (int q = 0; q < RREL; q++) {
        float lo, hi; upk2(acc[q], lo, hi);
        float lg = lo + hi;
        float y = gold[base + (size_t)q * LL];
        s += fmaxf(lg, 0.f) - lg * y + __logf(1.f + __expf(-fabsf(lg)));
    }
    s *= msk;
#pragma unroll
    for (int o = 16; o; o >>= 1) s += __shfl_down_sync(0xffffffffu, s, o);
    if ((tid & 31) == 0) red[tid >> 5] = s;
    __syncthreads();
    if (tid == 0) {
        float t = 0.f;
#pragma unroll
        for (int w = 0; w < 8; w++) t += red[w];
        g_selpart[(blockIdx.z * 8 + blockIdx.y) * 8 + blockIdx.x] = t;
    }
}

// ---------- 7) final reduction ----------
__global__ __launch_bounds__(256) void k_final(float *out) {
    __shared__ float sh[256];
    int tid = threadIdx.x;
    float s = 0.f;
    for (int v = tid; v < 1024; v += 256) s += g_selpart[v];
    sh[tid] = s; __syncthreads();
    for (int o = 128; o; o >>= 1) { if (tid < o) sh[tid] += sh[tid + o]; __syncthreads(); }
    if (tid == 0) {
        float crf = 0.f, ms = 0.f;
        for (int b2 = 0; b2 < BB; b2++) { crf += g_crf[b2]; ms += g_msum[b2]; }
        out[0] = -(crf / (float)BB) + sh[0] / ms;
    }
}

extern "C" void kernel_launch(void* const* d_in, const int* in_sizes, int n_in,
                              void* d_out, int out_size) {
    const int   *tokens = (const int  *)d_in[0];
    const int   *bio    = (const int  *)d_in[1];
    const float *gold   = (const float*)d_in[2];
    const float *wemb   = (const float*)d_in[3];
    const float *Wihf   = (const float*)d_in[4];
    const float *Whhf   = (const float*)d_in[5];
    const float *bf     = (const float*)d_in[6];
    const float *Wihb   = (const float*)d_in[7];
    const float *Whhb   = (const float*)d_in[8];
    const float *bbv    = (const float*)d_in[9];
    const float *emiW   = (const float*)d_in[10];
    const float *emib   = (const float*)d_in[11];
    const float *bioemb = (const float*)d_in[12];
    const float *suW    = (const float*)d_in[13];
    const float *sub    = (const float*)d_in[14];
    const float *svW    = (const float*)d_in[15];
    const float *svb    = (const float*)d_in[16];
    const float *suvW   = (const float*)d_in[17];
    const float *suvb   = (const float*)d_in[18];
    const float *rel    = (const float*)d_in[19];
    const float *cs     = (const float*)d_in[20];
    const float *ce     = (const float*)d_in[21];
    const float *ct     = (const float*)d_in[22];
    float *out = (float *)d_out;

    float *p_emb, *p_xg0, *p_xg1, *p_oc, *p_u, *p_v, *p_a, *p_c;
    cudaGetSymbolAddress((void**)&p_emb, g_emb);
    cudaGetSymbolAddress((void**)&p_xg0, g_xg0);
    cudaGetSymbolAddress((void**)&p_xg1, g_xg1);
    cudaGetSymbolAddress((void**)&p_oc,  g_oc);
    cudaGetSymbolAddress((void**)&p_u,   g_u);
    cudaGetSymbolAddress((void**)&p_v,   g_v);
    cudaGetSymbolAddress((void**)&p_a,   g_a);
    cudaGetSymbolAddress((void**)&p_c,   g_c);

    cudaFuncSetAttribute(k_lstm2, cudaFuncAttributeMaxDynamicSharedMemorySize, LSTM_SMEM);

    k_embed<<<ML, 64>>>(tokens, wemb);
    k_gemm<false, true><<<dim3(H4/64, ML/64), 256>>>(p_emb, EE, Wihf, EE, bf,  p_xg0, H4, EE);
    k_gemm<false, true><<<dim3(H4/64, ML/64), 256>>>(p_emb, EE, Wihb, EE, bbv, p_xg1, H4, EE);
    k_lstm2<<<64, 512, LSTM_SMEM>>>(Whhf, Whhb);
    k_combine<<<ML, 256>>>(bio, bioemb, emiW, emib);
    k_gemm<true,  true><<<dim3(RRr/64, ML/64), 256>>>(p_oc, HH+BIOd, suW, HH+BIOd, sub, p_u, RRr, HH+BIOd);
    k_gemm<true,  true><<<dim3(RRr/64, ML/64), 256>>>(p_oc, HH+BIOd, svW, HH+BIOd, svb, p_v, RRr, HH+BIOd);
    k_gemm<false, false><<<dim3(RRr/64, ML/64), 256>>>(p_u, RRr, suvW,        2*RRr, nullptr, p_a, RRr, RRr);
    k_gemm<false, false><<<dim3(RRr/64, ML/64), 256>>>(p_v, RRr, suvW + RRr,  2*RRr, nullptr, p_c, RRr, RRr);
    k_crf<<<1, 512>>>(tokens, bio, cs, ce, ct);
    k_sel<<<dim3(8, 8, BB), 256>>>(gold, tokens, suvb, rel);
    k_final<<<1, 256>>>(out);
}